// round 15
// baseline (speedup 1.0000x reference)
#include <cuda_runtime.h>
#include <math.h>

// ---------------- constants ----------------
#define B_   2
#define C_   64
#define CH_  32
#define H_   256
#define W_   256
#define HWv  65536
#define QKVC 320
#define NH_  4
#define HWP_ 16384

// radix sort config
#define R_ROWS 128
#define R_N    65536
#define R_SEG  4096
#define R_NSEG 16
#define R_THREADS 512
#define R_EPT  8

// qk slicing
#define QK_SL 64

// conv1x1 tiling
#define CV_PX 256
#define CV_SMEM (64*CV_PX*4 + 64*64*4)   // 81920 bytes

// sort_h tiled smem
#define SH_SMEM (256*33*4 + 2*256*33)    // 50688 bytes

// ---------------- scratch (static device memory; no allocs) ----------------
__device__ float g_xcat[B_*C_*HWv];            // only ch<32 used (sorted)
__device__ int   g_invh[B_*CH_*HWv];
__device__ int   g_invw[B_*CH_*HWv];
__device__ float g_qkv_pre[B_*QKVC*HWv];
__device__ float4 g_qkvi[B_*C_*HWv];           // interleaved {q1,k1,q2,k2}
__device__ unsigned g_keyA[R_ROWS*R_N];
__device__ unsigned g_keyB[R_ROWS*R_N];
__device__ unsigned short g_pidA[R_ROWS*R_N];
__device__ unsigned short g_pidB[R_ROWS*R_N];
__device__ unsigned g_histA[R_ROWS*256*R_NSEG];   // accumulated by dwconv_v (pass 1)
__device__ unsigned g_histB[R_ROWS*256*R_NSEG];   // written by rhist (passes 2-4)
__device__ int   g_idx[B_*C_*HWv];
__device__ float g_vs [B_*C_*HWv];
__device__ float g_norm[2048];
__device__ float g_npart[2048*QK_SL];
__device__ float g_Spart[16*QK_SL*4096];
__device__ float g_attn[16*4096];
__device__ float g_out1[B_*C_*HWv];
__device__ float g_prod[B_*C_*HWv];
__device__ float g_proj[B_*C_*HWv];            // only ch<32 used

// ---------------- helpers ----------------
__device__ __forceinline__ bool pair_gt(float va, int ia, float vb, int ib) {
    return (va > vb) || (va == vb && ia > ib);
}

__global__ void zero_histA_kernel() {
    size_t i = (size_t)blockIdx.x*256 + threadIdx.x;
    g_histA[i] = 0;
}

// ---------------- sort_h: tiled, coalesced (32 columns per block) ----------------
__global__ void __launch_bounds__(256)
sort_h_kernel(const float* __restrict__ x) {
    extern __shared__ char shm[];
    float* sv = (float*)shm;                          // [256][33]
    unsigned char* si  = (unsigned char*)(sv + 256*33);
    unsigned char* inv = si + 256*33;
    int blk = blockIdx.x;
    int b = blk / (CH_*(W_/32));
    int c = (blk / (W_/32)) % CH_;
    int w0 = (blk % (W_/32)) * 32;
    int t = threadIdx.x;
    int lane = t & 31, wrow = t >> 5;
    const float* xp = x + ((size_t)(b*C_ + c))*HWv + w0;
#pragma unroll 4
    for (int r = 0; r < 32; r++) {
        int row = r*8 + wrow;
        sv[row*33 + lane] = xp[(size_t)row*W_ + lane];
        si[row*33 + lane] = (unsigned char)row;
    }
    __syncthreads();
    int col = t & 31;
    int grp = t >> 5;
    for (int k = 2; k <= 256; k <<= 1) {
        for (int j = k >> 1; j > 0; j >>= 1) {
#pragma unroll 4
            for (int pp = 0; pp < 16; pp++) {
                int idx = grp*16 + pp;
                int i = ((idx & ~(j-1)) << 1) | (idx & (j-1));
                int partner = i | j;
                bool up = ((i & k) == 0);
                float va = sv[i*33 + col], vb = sv[partner*33 + col];
                int   ia = si[i*33 + col], ib = si[partner*33 + col];
                bool sw = up ? pair_gt(va, ia, vb, ib) : pair_gt(vb, ib, va, ia);
                if (sw) {
                    sv[i*33 + col] = vb;       si[i*33 + col] = (unsigned char)ib;
                    sv[partner*33 + col] = va; si[partner*33 + col] = (unsigned char)ia;
                }
            }
            __syncthreads();
        }
    }
    float* xo = g_xcat + ((size_t)(b*C_ + c))*HWv + w0;
#pragma unroll 4
    for (int r = 0; r < 32; r++) {
        int row = r*8 + wrow;
        xo[(size_t)row*W_ + lane] = sv[row*33 + lane];
        inv[(int)si[row*33 + lane]*33 + lane] = (unsigned char)row;
    }
    __syncthreads();
    int* io = g_invh + ((size_t)(b*CH_ + c))*HWv + w0;
#pragma unroll 4
    for (int r = 0; r < 32; r++) {
        int row = r*8 + wrow;
        io[(size_t)row*W_ + lane] = inv[row*33 + lane];
    }
}

// ---------------- sort_w ----------------
__device__ __forceinline__ void bitonic256(float* sv, int* si) {
    int t = threadIdx.x;
    for (int k = 2; k <= 256; k <<= 1) {
        for (int j = k >> 1; j > 0; j >>= 1) {
            int ixj = t ^ j;
            if (ixj > t) {
                bool up = ((t & k) == 0);
                float va = sv[t], vb = sv[ixj];
                int   ia = si[t], ib = si[ixj];
                bool sw = up ? pair_gt(va, ia, vb, ib) : pair_gt(vb, ib, va, ia);
                if (sw) { sv[t] = vb; si[t] = ib; sv[ixj] = va; si[ixj] = ia; }
            }
            __syncthreads();
        }
    }
}

__global__ void sort_w_kernel() {
    __shared__ float sv[256];
    __shared__ int   si[256];
    int blk = blockIdx.x;
    int b = blk / (CH_*H_);
    int c = (blk / H_) % CH_;
    int h = blk % H_;
    int t = threadIdx.x;
    float* base = g_xcat + ((size_t)(b*C_ + c))*HWv + (size_t)h*W_;
    sv[t] = base[t];
    si[t] = t;
    __syncthreads();
    bitonic256(sv, si);
    base[t] = sv[t];
    g_invw[((size_t)(b*CH_ + c))*HWv + (size_t)h*W_ + si[t]] = t;
}

// ---------------- conv1x1 (split input/output) ----------------
__global__ void __launch_bounds__(256)
conv1x1_kernel(const float* __restrict__ inA, const float* __restrict__ inB,
               const float* __restrict__ w,
               float* __restrict__ outA, float* __restrict__ outB,
               int OC, int oc_split) {
    extern __shared__ float sm[];
    float* Xs = sm;                 // [64][256]
    float* Ws = sm + 64*CV_PX;      // [64][64]
    int p0  = blockIdx.x * CV_PX;
    int oc0 = blockIdx.y * 64;
    int b   = blockIdx.z;
    int t   = threadIdx.x;
#pragma unroll
    for (int r = 0; r < 16; r++) {
        int l = r*256 + t; int ic = l >> 6; int grp = l & 63;
        const float* src = (ic < 32) ? inA : inB;
        *(float4*)&Xs[ic*CV_PX + grp*4] =
            *(const float4*)&src[((size_t)(b*64 + ic))*HWv + p0 + grp*4];
    }
#pragma unroll
    for (int r = 0; r < 16; r++) {
        int l = r*256 + t; int oc = l >> 6; int ic = l & 63;
        Ws[ic*64 + oc] = w[(size_t)(oc0 + oc)*64 + ic];
    }
    __syncthreads();
    int tx = t & 31, ty = t >> 5;
    float acc[8][8];
#pragma unroll
    for (int i = 0; i < 8; i++)
#pragma unroll
        for (int j = 0; j < 8; j++) acc[i][j] = 0.f;
#pragma unroll
    for (int ic = 0; ic < 64; ic++) {
        float4 xa = *(const float4*)&Xs[ic*CV_PX + tx*4];
        float4 xb = *(const float4*)&Xs[ic*CV_PX + 128 + tx*4];
        float4 wa = *(const float4*)&Ws[ic*64 + ty*8];
        float4 wb = *(const float4*)&Ws[ic*64 + ty*8 + 4];
        float xv[8] = {xa.x,xa.y,xa.z,xa.w,xb.x,xb.y,xb.z,xb.w};
        float wv[8] = {wa.x,wa.y,wa.z,wa.w,wb.x,wb.y,wb.z,wb.w};
#pragma unroll
        for (int i = 0; i < 8; i++)
#pragma unroll
            for (int j = 0; j < 8; j++) acc[i][j] += wv[i]*xv[j];
    }
#pragma unroll
    for (int i = 0; i < 8; i++) {
        int oc = oc0 + ty*8 + i;
        float* dst = (oc < oc_split) ? outA : outB;
        size_t ob = ((size_t)(b*OC + oc))*HWv + p0;
        *(float4*)&dst[ob + tx*4]       = make_float4(acc[i][0],acc[i][1],acc[i][2],acc[i][3]);
        *(float4*)&dst[ob + 128 + tx*4] = make_float4(acc[i][4],acc[i][5],acc[i][6],acc[i][7]);
    }
}

// ---------------- depthwise 3x3: qk planes ----------------
__global__ void __launch_bounds__(256)
dwconv_qk_kernel(const float* __restrict__ in, const float* __restrict__ wd) {
    __shared__ float tile[4][10][W_];   // 40KB
    int bid = blockIdx.x;
    int hblk = bid & 31;
    int cb = bid >> 5;
    int c = cb % 64;
    int b = cb / 64;
    int h0 = hblk * 8;
    int t = threadIdx.x;
#pragma unroll
    for (int p = 0; p < 4; p++) {
        const float* ip = in + ((size_t)(b*QKVC + p*64 + c))*HWv;
#pragma unroll
        for (int r = 0; r < 10; r++) {
            int hh = h0 - 1 + r;
            tile[p][r][t] = (hh >= 0 && hh < H_) ? ip[(size_t)hh*W_ + t] : 0.f;
        }
    }
    __syncthreads();

    float o[4][8];
#pragma unroll
    for (int p = 0; p < 4; p++) {
        float wreg[9];
#pragma unroll
        for (int i = 0; i < 9; i++) wreg[i] = __ldg(&wd[(size_t)(p*64 + c)*9 + i]);
        float wl[10], wm[10], wr[10];
#pragma unroll
        for (int r = 0; r < 10; r++) {
            wm[r] = tile[p][r][t];
            wl[r] = (t > 0)   ? tile[p][r][t-1] : 0.f;
            wr[r] = (t < 255) ? tile[p][r][t+1] : 0.f;
        }
#pragma unroll
        for (int r = 0; r < 8; r++) {
            o[p][r] = wl[r  ]*wreg[0] + wm[r  ]*wreg[1] + wr[r  ]*wreg[2]
                    + wl[r+1]*wreg[3] + wm[r+1]*wreg[4] + wr[r+1]*wreg[5]
                    + wl[r+2]*wreg[6] + wm[r+2]*wreg[7] + wr[r+2]*wreg[8];
        }
    }
    float4* op = g_qkvi + ((size_t)(b*64 + c))*HWv;
#pragma unroll
    for (int r = 0; r < 8; r++) {
        op[(h0 + r)*W_ + t] = make_float4(o[0][r], o[1][r], o[2][r], o[3][r]);
    }
}

// ---------------- depthwise 3x3: v channels -> keys + digit-0 histogram ----------------
__global__ void __launch_bounds__(256)
dwconv_v_kernel(const float* __restrict__ in, const float* __restrict__ wd) {
    __shared__ float tile[10][W_];
    __shared__ unsigned hloc[256];
    int bid = blockIdx.x;
    int hblk = bid & 31;
    int cb = bid >> 5;
    int c = cb % 64;
    int b = cb / 64;
    int ch = 256 + c;
    int h0 = hblk * 8;
    int t = threadIdx.x;
    hloc[t] = 0;
    const float* ip = in + ((size_t)(b*QKVC + ch))*HWv;
#pragma unroll
    for (int r = 0; r < 10; r++) {
        int hh = h0 - 1 + r;
        tile[r][t] = (hh >= 0 && hh < H_) ? ip[(size_t)hh*W_ + t] : 0.f;
    }
    float wreg[9];
#pragma unroll
    for (int i = 0; i < 9; i++) wreg[i] = __ldg(&wd[(size_t)ch*9 + i]);
    __syncthreads();

    float wl[10], wm[10], wr[10];
#pragma unroll
    for (int r = 0; r < 10; r++) {
        wm[r] = tile[r][t];
        wl[r] = (t > 0)   ? tile[r][t-1] : 0.f;
        wr[r] = (t < 255) ? tile[r][t+1] : 0.f;
    }
    int row = b*64 + c;
    unsigned* kp = g_keyA + (size_t)row*HWv;
#pragma unroll
    for (int r = 0; r < 8; r++) {
        float s = wl[r  ]*wreg[0] + wm[r  ]*wreg[1] + wr[r  ]*wreg[2]
                + wl[r+1]*wreg[3] + wm[r+1]*wreg[4] + wr[r+1]*wreg[5]
                + wl[r+2]*wreg[6] + wm[r+2]*wreg[7] + wr[r+2]*wreg[8];
        unsigned u = __float_as_uint(s);
        u ^= (u & 0x80000000u) ? 0xFFFFFFFFu : 0x80000000u;
        kp[(h0 + r)*W_ + t] = u;
        atomicAdd(&hloc[u & 255u], 1u);
    }
    __syncthreads();
    int seg = hblk >> 1;
    unsigned v = hloc[t];
    if (v) atomicAdd(&g_histA[((size_t)row*256 + t)*R_NSEG + seg], v);
}

// ---------------- rhist (passes 2-4): uint4-vectorized, plain store ----------------
__global__ void rhist_kernel(const unsigned* __restrict__ src, unsigned* __restrict__ hist,
                             int shift) {
    __shared__ unsigned h[256];
    int row = blockIdx.x >> 4, seg = blockIdx.x & 15;
    int tid = threadIdx.x;
    if (tid < 256) h[tid] = 0;
    __syncthreads();
    const uint4* s = (const uint4*)(src + (size_t)row*R_N + (size_t)seg*R_SEG);
#pragma unroll
    for (int r = 0; r < 2; r++) {
        uint4 k4 = s[r*R_THREADS + tid];
        atomicAdd(&h[(k4.x >> shift) & 255u], 1u);
        atomicAdd(&h[(k4.y >> shift) & 255u], 1u);
        atomicAdd(&h[(k4.z >> shift) & 255u], 1u);
        atomicAdd(&h[(k4.w >> shift) & 255u], 1u);
    }
    __syncthreads();
    if (tid < 256)
        hist[((size_t)row*256 + tid)*R_NSEG + seg] = h[tid];
}

// ---------------- scan ----------------
__global__ void rscan_kernel(unsigned* __restrict__ hist) {
    int row = blockIdx.x, dg = threadIdx.x;
    unsigned* hp = hist + ((size_t)row*256 + dg)*R_NSEG;
    unsigned v[R_NSEG]; unsigned tot = 0;
#pragma unroll
    for (int s2 = 0; s2 < R_NSEG; s2++) { unsigned t = hp[s2]; v[s2] = tot; tot += t; }
    unsigned lane = dg & 31, w = dg >> 5;
    unsigned x = tot;
#pragma unroll
    for (int o = 1; o < 32; o <<= 1) { unsigned y = __shfl_up_sync(0xffffffffu, x, o); if (lane >= o) x += y; }
    __shared__ unsigned wsum[8];
    if (lane == 31) wsum[w] = x;
    __syncthreads();
    if (dg == 0) { unsigned run = 0; for (int i = 0; i < 8; i++) { unsigned t = wsum[i]; wsum[i] = run; run += t; } }
    __syncthreads();
    unsigned base0 = (x - tot) + wsum[w];
#pragma unroll
    for (int s2 = 0; s2 < R_NSEG; s2++) hp[s2] = base0 + v[s2];
}

// mode: 1 = first pass (generate payload), 0 = middle, 2 = final (emit idx+vs)
__global__ void __launch_bounds__(R_THREADS)
rscatter_kernel(const unsigned* __restrict__ skeys,
                const unsigned short* __restrict__ spids,
                unsigned* __restrict__ dkeys,
                unsigned short* __restrict__ dpids,
                const unsigned* __restrict__ hist,
                int shift, int mode) {
    __shared__ unsigned base[256];
    __shared__ unsigned bb0[256];
    __shared__ unsigned delta[256];
    __shared__ unsigned scanbuf[8];
    __shared__ unsigned skey[R_SEG];          // 16KB; doubles as woff
    __shared__ unsigned short spid[R_SEG];    // 8KB;  doubles as wcnt
    unsigned short* wcnt = spid;
    unsigned*       woff = skey;
    unsigned*       wc32 = (unsigned*)wcnt;

    int row = blockIdx.x >> 4, seg = blockIdx.x & 15;
    int tid = threadIdx.x, w = tid >> 5, lane = tid & 31;
    const unsigned* sk = skeys + (size_t)row*R_N + (size_t)seg*R_SEG;

    unsigned key[R_EPT];
    unsigned pid[R_EPT];
    unsigned posG[R_EPT];
#pragma unroll
    for (int r = 0; r < R_EPT; r++) key[r] = sk[r*R_THREADS + tid];
    if (mode == 1) {
#pragma unroll
        for (int r = 0; r < R_EPT; r++) pid[r] = seg*R_SEG + r*R_THREADS + tid;
    } else {
        const unsigned short* sp = spids + (size_t)row*R_N + (size_t)seg*R_SEG;
#pragma unroll
        for (int r = 0; r < R_EPT; r++) pid[r] = sp[r*R_THREADS + tid];
    }

    if (tid < 256) {
        unsigned bv = hist[((size_t)row*256 + tid)*R_NSEG + seg];
        base[tid] = bv; bb0[tid] = bv;
    }

#pragma unroll
    for (int r = 0; r < R_EPT; r++) {
        wc32[tid] = 0; wc32[tid + 512] = 0; wc32[tid + 1024] = 0; wc32[tid + 1536] = 0;
        unsigned dg = (key[r] >> shift) & 255u;
        unsigned mask = __match_any_sync(0xffffffffu, dg);
        unsigned lr = __popc(mask & ((1u << lane) - 1u));
        unsigned cnt = __popc(mask);
        __syncthreads();
        if (lr == 0) wcnt[w*256 + dg] = (unsigned short)cnt;
        __syncthreads();
        if (tid < 256) {
            unsigned run = base[tid];
#pragma unroll
            for (int ww = 0; ww < 16; ww++) {
                unsigned c2 = wcnt[ww*256 + tid];
                woff[ww*256 + tid] = run;
                run += c2;
            }
            base[tid] = run;
        }
        __syncthreads();
        posG[r] = woff[w*256 + dg] + lr;
    }
    __syncthreads();

    if (tid < 256) {
        unsigned c = base[tid] - bb0[tid];
        unsigned x = c;
#pragma unroll
        for (int o = 1; o < 32; o <<= 1) { unsigned y = __shfl_up_sync(0xffffffffu, x, o); if (lane >= o) x += y; }
        woff[tid] = x - c;
        if (lane == 31) scanbuf[w] = x;
    }
    __syncthreads();
    if (tid == 0) { unsigned run = 0; for (int i = 0; i < 8; i++) { unsigned t2 = scanbuf[i]; scanbuf[i] = run; run += t2; } }
    __syncthreads();
    if (tid < 256) delta[tid] = bb0[tid] - (woff[tid] + scanbuf[tid >> 5]);
    __syncthreads();

#pragma unroll
    for (int r = 0; r < R_EPT; r++) {
        unsigned dg = (key[r] >> shift) & 255u;
        unsigned loc = posG[r] - delta[dg];
        skey[loc] = key[r];
        spid[loc] = (unsigned short)pid[r];
    }
    __syncthreads();

    if (mode != 2) {
        unsigned* dk = dkeys + (size_t)row*R_N;
        unsigned short* dp = dpids + (size_t)row*R_N;
#pragma unroll
        for (int r = 0; r < R_EPT; r++) {
            unsigned i = r*R_THREADS + tid;
            unsigned k2 = skey[i];
            unsigned dg = (k2 >> shift) & 255u;
            unsigned pos = delta[dg] + i;
            dk[pos] = k2;
            dp[pos] = spid[i];
        }
    } else {
        int*   di = g_idx + (size_t)row*R_N;
        float* dv = g_vs  + (size_t)row*R_N;
#pragma unroll
        for (int r = 0; r < R_EPT; r++) {
            unsigned i = r*R_THREADS + tid;
            unsigned k2 = skey[i];
            unsigned dg = (k2 >> shift) & 255u;
            unsigned pos = delta[dg] + i;
            unsigned u = (k2 & 0x80000000u) ? (k2 ^ 0x80000000u) : ~k2;
            di[pos] = (int)spid[i];
            dv[pos] = __uint_as_float(u);
        }
    }
}

// ---------------- attention: qk ----------------
__global__ void qk_kernel() {
    __shared__ float Qs[64][65];
    __shared__ float Ks[64][65];
    __shared__ float nred[2][4][64];
    int t = threadIdx.x;
    int vbh = blockIdx.y;
    int var = vbh >> 3, b = (vbh>>2)&1, h = vbh & 3;
    int ty = t >> 4, tx = t & 15;
    int dn = t & 63, qtr = t >> 6;
    float acc[4][4];
#pragma unroll
    for (int i = 0; i < 4; i++)
#pragma unroll
        for (int j = 0; j < 4; j++) acc[i][j] = 0.f;
    float sumq = 0.f, sumk = 0.f;
    int n0 = blockIdx.x * 256;
    for (int tile = 0; tile < 4; tile++) {
        int nb = n0 + tile*64;
#pragma unroll
        for (int rr = 0; rr < 16; rr++) {
            int l = rr*256 + t; int d = l >> 6; int nn = l & 63;
            int c = h*16 + (d>>2), f = d & 3;
            int pos = var ? 4*(nb+nn) + f : f*HWP_ + nb + nn;
            size_t rowb = ((size_t)(b*64 + c))*HWv;
            int j = g_idx[rowb + pos];
            float4 v4 = g_qkvi[rowb + j];
            Qs[d][nn] = var ? v4.z : v4.x;
            Ks[d][nn] = var ? v4.w : v4.y;
        }
        __syncthreads();
#pragma unroll
        for (int i = 0; i < 16; i++) {
            float qv = Qs[dn][qtr*16 + i];
            float kv = Ks[dn][qtr*16 + i];
            sumq += qv*qv; sumk += kv*kv;
        }
#pragma unroll 8
        for (int nn = 0; nn < 64; nn++) {
            float qa[4], ka[4];
#pragma unroll
            for (int i = 0; i < 4; i++) { qa[i] = Qs[ty*4+i][nn]; ka[i] = Ks[tx*4+i][nn]; }
#pragma unroll
            for (int i = 0; i < 4; i++)
#pragma unroll
                for (int j = 0; j < 4; j++) acc[i][j] += qa[i]*ka[j];
        }
        __syncthreads();
    }
    nred[0][qtr][dn] = sumq;
    nred[1][qtr][dn] = sumk;
    float* sp = g_Spart + ((size_t)(vbh*QK_SL + blockIdx.x))*4096;
#pragma unroll
    for (int i = 0; i < 4; i++)
#pragma unroll
        for (int j = 0; j < 4; j++)
            sp[(ty*4+i)*64 + tx*4 + j] = acc[i][j];
    __syncthreads();
    if (t < 128) {
        int qk = t >> 6, d = t & 63;
        float s = nred[qk][0][d] + nred[qk][1][d] + nred[qk][2][d] + nred[qk][3][d];
        int bin = (var<<10) | (qk<<9) | (b<<8) | (h<<6) | d;
        g_npart[(size_t)bin*QK_SL + blockIdx.x] = s;
    }
}

__global__ void reduce_norm_kernel() {
    int bin = blockIdx.x * 128 + threadIdx.x;
    const float* p = g_npart + (size_t)bin*QK_SL;
    float s = 0.f;
#pragma unroll
    for (int i = 0; i < QK_SL; i++) s += p[i];
    g_norm[bin] = 1.0f / fmaxf(sqrtf(s), 1e-12f);
}

__global__ void softmax_kernel(const float* __restrict__ temp) {
    int blk = blockIdx.x;
    int vbh = blk >> 6, d = blk & 63;
    int var = vbh >> 3, b = (vbh>>2)&1, h = vbh & 3;
    int e = threadIdx.x;
    float sk = g_norm[(var<<10) | (1<<9) | (b<<8) | (h<<6) | e];
    float invq = g_norm[(var<<10) | (b<<8) | (h<<6) | d];
    float T = temp[h];
    const float* sp = g_Spart + (size_t)vbh*QK_SL*4096 + d*64 + e;
    float s = 0.f;
#pragma unroll
    for (int sl = 0; sl < QK_SL; sl++) s += sp[(size_t)sl*4096];
    float ex = expf(s * invq * sk * T);
    __shared__ float red[64];
    red[e] = ex;
    __syncthreads();
    if (e < 32) {
        float p = red[e] + red[e + 32];
#pragma unroll
        for (int o = 16; o > 0; o >>= 1) p += __shfl_down_sync(0xffffffffu, p, o);
        if (e == 0) red[0] = p;
    }
    __syncthreads();
    float r = 1.0f / (red[0] + 1.0f);
    g_attn[(size_t)vbh*4096 + d*64 + e] = ex * r;
}

// av var=0: writes g_out1
__global__ void av0_kernel() {
    __shared__ float As[4096];
    int t = threadIdx.x;
    int bid = blockIdx.x;                 // 512: (b,h,nblk)
    int nblk = bid & 63;
    int h = (bid>>6)&3, b = (bid>>8)&1;
    int vbh = (b<<2) | h;
    for (int l = t; l < 4096; l += 256) As[l] = g_attn[(size_t)vbh*4096 + l];
    __syncthreads();
    int n = nblk*256 + t;
    float acc[64];
#pragma unroll
    for (int d2 = 0; d2 < 64; d2++) acc[d2] = 0.f;
#pragma unroll 4
    for (int e0 = 0; e0 < 64; e0 += 4) {
        int ce = h*16 + (e0 >> 2);
        size_t cb = ((size_t)(b*64 + ce))*HWv;
        float v0 = g_vs[cb + n];
        float v1 = g_vs[cb + HWP_ + n];
        float v2 = g_vs[cb + 2*HWP_ + n];
        float v3 = g_vs[cb + 3*HWP_ + n];
#pragma unroll
        for (int d2 = 0; d2 < 64; d2++) {
            float4 a = *(const float4*)&As[d2*64 + e0];
            acc[d2] += a.x*v0 + a.y*v1 + a.z*v2 + a.w*v3;
        }
    }
#pragma unroll 1
    for (int d2 = 0; d2 < 64; d2++) {
        int cd = h*16 + (d2>>2), fd = d2 & 3;
        g_out1[((size_t)(b*64 + cd))*HWv + (size_t)fd*HWP_ + n] = acc[d2];
    }
}

// av var=1 fused with product + scatter
__global__ void av1_kernel() {
    __shared__ float As[4096];
    int t = threadIdx.x;
    int bid = blockIdx.x;                 // 512
    int nblk = bid & 63;
    int h = (bid>>6)&3, b = (bid>>8)&1;
    int vbh = 8 | (b<<2) | h;
    for (int l = t; l < 4096; l += 256) As[l] = g_attn[(size_t)vbh*4096 + l];
    __syncthreads();
    int n = nblk*256 + t;
    float acc[64];
#pragma unroll
    for (int d2 = 0; d2 < 64; d2++) acc[d2] = 0.f;
#pragma unroll 4
    for (int e0 = 0; e0 < 64; e0 += 4) {
        int ce = h*16 + (e0 >> 2);
        size_t cb = ((size_t)(b*64 + ce))*HWv;
        float4 vv = *(const float4*)&g_vs[cb + 4*(size_t)n];
#pragma unroll
        for (int d2 = 0; d2 < 64; d2++) {
            float4 a = *(const float4*)&As[d2*64 + e0];
            acc[d2] += a.x*vv.x + a.y*vv.y + a.z*vv.z + a.w*vv.w;
        }
    }
#pragma unroll 1
    for (int cg = 0; cg < 16; cg++) {
        int cd = h*16 + cg;
        size_t rb = ((size_t)(b*64 + cd))*HWv;
        size_t pos = rb + 4*(size_t)n;
        float4 o1 = *(const float4*)&g_out1[pos];
        int4   j4 = *(const int4*)&g_idx[pos];
        g_prod[rb + j4.x] = acc[cg*4 + 0] * o1.x;
        g_prod[rb + j4.y] = acc[cg*4 + 1] * o1.y;
        g_prod[rb + j4.z] = acc[cg*4 + 2] * o1.z;
        g_prod[rb + j4.w] = acc[cg*4 + 3] * o1.w;
    }
}

// ---------------- fused unsort (ch<32 only) ----------------
__global__ void unsort_kernel(float* __restrict__ out) {
    size_t gid = (size_t)blockIdx.x*256 + threadIdx.x;   // B*CH*HW
    size_t bc = gid / HWv;
    int b = (int)(bc / CH_), c = (int)(bc % CH_);
    int p = (int)(gid % HWv);
    int j = p & 255;
    int r = g_invh[bc*HWv + p];
    int jw = g_invw[bc*HWv + (size_t)r*W_ + j];
    out[((size_t)(b*C_ + c))*HWv + p] = g_proj[((size_t)(b*C_ + c))*HWv + (size_t)r*W_ + jw];
}

// ---------------- launch ----------------
extern "C" void kernel_launch(void* const* d_in, const int* in_sizes, int n_in,
                              void* d_out, int out_size) {
    const float* x     = (const float*)d_in[0];
    const float* qkvw  = (const float*)d_in[1];
    const float* dww   = (const float*)d_in[2];
    const float* projw = (const float*)d_in[3];
    const float* temp  = (const float*)d_in[4];
    float* out = (float*)d_out;

    cudaFuncSetAttribute((const void*)conv1x1_kernel,
                         cudaFuncAttributeMaxDynamicSharedMemorySize, CV_SMEM);
    cudaFuncSetAttribute((const void*)sort_h_kernel,
                         cudaFuncAttributeMaxDynamicSharedMemorySize, SH_SMEM);

    // side stream + events for overlapping dwconv_qk with the sort chain.
    // Created fresh per call (host-side objects only; deterministic work).
    cudaStream_t s2;
    cudaEvent_t evA, evB;
    cudaStreamCreateWithFlags(&s2, cudaStreamNonBlocking);
    cudaEventCreateWithFlags(&evA, cudaEventDisableTiming);
    cudaEventCreateWithFlags(&evB, cudaEventDisableTiming);

    float *p_xcat, *p_qkvpre, *p_prod, *p_proj;
    unsigned *p_kA, *p_kB, *p_hA, *p_hB;
    unsigned short *p_pA, *p_pB;
    cudaGetSymbolAddress((void**)&p_xcat,   g_xcat);
    cudaGetSymbolAddress((void**)&p_qkvpre, g_qkv_pre);
    cudaGetSymbolAddress((void**)&p_prod,   g_prod);
    cudaGetSymbolAddress((void**)&p_proj,   g_proj);
    cudaGetSymbolAddress((void**)&p_kA,     g_keyA);
    cudaGetSymbolAddress((void**)&p_kB,     g_keyB);
    cudaGetSymbolAddress((void**)&p_pA,     g_pidA);
    cudaGetSymbolAddress((void**)&p_pB,     g_pidB);
    cudaGetSymbolAddress((void**)&p_hA,     g_histA);
    cudaGetSymbolAddress((void**)&p_hB,     g_histB);

    const int NBCH = (B_*CH_*HWv) / 256;    // 16384

    // stage A: zero histA + small sorts
    zero_histA_kernel<<<(R_ROWS*256*R_NSEG)/256, 256>>>();
    sort_h_kernel<<<B_*CH_*(W_/32), 256, SH_SMEM>>>(x);
    sort_w_kernel<<<B_*CH_*H_, 256>>>();

    // stage B: conv, then fork: dwconv_qk on s2 || dwconv_v + sort on main
    conv1x1_kernel<<<dim3(HWv/CV_PX, QKVC/64, B_), 256, CV_SMEM>>>(
        p_xcat, x, qkvw, p_qkvpre, p_qkvpre, QKVC, QKVC);
    cudaEventRecord(evA, 0);
    cudaStreamWaitEvent(s2, evA, 0);
    dwconv_qk_kernel<<<B_*64*32, 256, 0, s2>>>(p_qkvpre, dww);
    cudaEventRecord(evB, s2);

    dwconv_v_kernel<<<B_*64*32, 256>>>(p_qkvpre, dww);

    // stage C: big stable argsort (pass-1 hist fused into dwconv_v)
    {
        const int NB = R_ROWS * R_NSEG;   // 2048
        rscan_kernel<<<R_ROWS, 256>>>(p_hA);
        rscatter_kernel<<<NB, R_THREADS>>>(p_kA, (const unsigned short*)0, p_kB, p_pB,
                                           p_hA, 0, 1);
        rhist_kernel<<<NB, R_THREADS>>>(p_kB, p_hB, 8);
        rscan_kernel<<<R_ROWS, 256>>>(p_hB);
        rscatter_kernel<<<NB, R_THREADS>>>(p_kB, p_pB, p_kA, p_pA, p_hB, 8, 0);

        rhist_kernel<<<NB, R_THREADS>>>(p_kA, p_hA, 16);
        rscan_kernel<<<R_ROWS, 256>>>(p_hA);
        rscatter_kernel<<<NB, R_THREADS>>>(p_kA, p_pA, p_kB, p_pB, p_hA, 16, 0);

        rhist_kernel<<<NB, R_THREADS>>>(p_kB, p_hB, 24);
        rscan_kernel<<<R_ROWS, 256>>>(p_hB);
        rscatter_kernel<<<NB, R_THREADS>>>(p_kB, p_pB, (unsigned*)0, (unsigned short*)0,
                                           p_hB, 24, 2);
    }

    // join: qk needs g_qkvi from s2
    cudaStreamWaitEvent(0, evB, 0);

    // stage D: attention
    qk_kernel<<<dim3(QK_SL, 16), 256>>>();
    reduce_norm_kernel<<<16, 128>>>();
    softmax_kernel<<<16*64, 64>>>(temp);
    av0_kernel<<<512, 256>>>();
    av1_kernel<<<512, 256>>>();

    // stage E: epilogue
    conv1x1_kernel<<<dim3(HWv/CV_PX, 1, B_), 256, CV_SMEM>>>(
        p_prod, p_prod, projw, p_proj, out, C_, CH_);
    unsort_kernel<<<NBCH, 256>>>(out);
}

// round 16
// speedup vs baseline: 1.0371x; 1.0371x over previous
#include <cuda_runtime.h>
#include <math.h>

// ---------------- constants ----------------
#define B_   2
#define C_   64
#define CH_  32
#define H_   256
#define W_   256
#define HWv  65536
#define QKVC 320
#define NH_  4
#define HWP_ 16384

// radix sort config
#define R_ROWS 128
#define R_N    65536
#define R_SEG  4096
#define R_NSEG 16
#define R_THREADS 512
#define R_EPT  8

// qk slicing
#define QK_SL 64

// conv1x1 tiling
#define CV_PX 256
#define CV_SMEM (64*CV_PX*4 + 64*64*4)   // 81920 bytes

// sort_h tiled smem
#define SH_SMEM (256*33*4 + 2*256*33)    // 50688 bytes

// ---------------- scratch (static device memory; no allocs) ----------------
__device__ float g_xcat[B_*C_*HWv];            // only ch<32 used (sorted)
__device__ int   g_invh[B_*CH_*HWv];
__device__ int   g_invw[B_*CH_*HWv];
__device__ float g_qkv_pre[B_*QKVC*HWv];
__device__ float2 g_qk1[B_*C_*HWv];            // {q1,k1}
__device__ float2 g_qk2[B_*C_*HWv];            // {q2,k2}
__device__ unsigned g_keyA[R_ROWS*R_N];
__device__ unsigned g_keyB[R_ROWS*R_N];
__device__ unsigned short g_pidA[R_ROWS*R_N];
__device__ unsigned short g_pidB[R_ROWS*R_N];
__device__ unsigned g_histA[R_ROWS*256*R_NSEG];   // accumulated by dwconv_v (pass 1)
__device__ unsigned g_histB[R_ROWS*256*R_NSEG];   // written by rhist (passes 2-4)
__device__ int   g_idx[B_*C_*HWv];
__device__ float g_vs [B_*C_*HWv];
__device__ float g_norm[2048];
__device__ float g_npart[2048*QK_SL];
__device__ float g_Spart[16*QK_SL*4096];
__device__ float g_attn[16*4096];
__device__ float g_out1[B_*C_*HWv];
__device__ float g_prod[B_*C_*HWv];
__device__ float g_proj[B_*C_*HWv];            // only ch<32 used

// ---------------- helpers ----------------
__device__ __forceinline__ bool pair_gt(float va, int ia, float vb, int ib) {
    return (va > vb) || (va == vb && ia > ib);
}

__global__ void zero_histA_kernel() {
    size_t i = (size_t)blockIdx.x*256 + threadIdx.x;
    g_histA[i] = 0;
}

// ---------------- sort_h: tiled, coalesced (32 columns per block) ----------------
__global__ void __launch_bounds__(256)
sort_h_kernel(const float* __restrict__ x) {
    extern __shared__ char shm[];
    float* sv = (float*)shm;                          // [256][33]
    unsigned char* si  = (unsigned char*)(sv + 256*33);
    unsigned char* inv = si + 256*33;
    int blk = blockIdx.x;
    int b = blk / (CH_*(W_/32));
    int c = (blk / (W_/32)) % CH_;
    int w0 = (blk % (W_/32)) * 32;
    int t = threadIdx.x;
    int lane = t & 31, wrow = t >> 5;
    const float* xp = x + ((size_t)(b*C_ + c))*HWv + w0;
#pragma unroll 4
    for (int r = 0; r < 32; r++) {
        int row = r*8 + wrow;
        sv[row*33 + lane] = xp[(size_t)row*W_ + lane];
        si[row*33 + lane] = (unsigned char)row;
    }
    __syncthreads();
    int col = t & 31;
    int grp = t >> 5;
    for (int k = 2; k <= 256; k <<= 1) {
        for (int j = k >> 1; j > 0; j >>= 1) {
#pragma unroll 4
            for (int pp = 0; pp < 16; pp++) {
                int idx = grp*16 + pp;
                int i = ((idx & ~(j-1)) << 1) | (idx & (j-1));
                int partner = i | j;
                bool up = ((i & k) == 0);
                float va = sv[i*33 + col], vb = sv[partner*33 + col];
                int   ia = si[i*33 + col], ib = si[partner*33 + col];
                bool sw = up ? pair_gt(va, ia, vb, ib) : pair_gt(vb, ib, va, ia);
                if (sw) {
                    sv[i*33 + col] = vb;       si[i*33 + col] = (unsigned char)ib;
                    sv[partner*33 + col] = va; si[partner*33 + col] = (unsigned char)ia;
                }
            }
            __syncthreads();
        }
    }
    float* xo = g_xcat + ((size_t)(b*C_ + c))*HWv + w0;
#pragma unroll 4
    for (int r = 0; r < 32; r++) {
        int row = r*8 + wrow;
        xo[(size_t)row*W_ + lane] = sv[row*33 + lane];
        inv[(int)si[row*33 + lane]*33 + lane] = (unsigned char)row;
    }
    __syncthreads();
    int* io = g_invh + ((size_t)(b*CH_ + c))*HWv + w0;
#pragma unroll 4
    for (int r = 0; r < 32; r++) {
        int row = r*8 + wrow;
        io[(size_t)row*W_ + lane] = inv[row*33 + lane];
    }
}

// ---------------- sort_w ----------------
__device__ __forceinline__ void bitonic256(float* sv, int* si) {
    int t = threadIdx.x;
    for (int k = 2; k <= 256; k <<= 1) {
        for (int j = k >> 1; j > 0; j >>= 1) {
            int ixj = t ^ j;
            if (ixj > t) {
                bool up = ((t & k) == 0);
                float va = sv[t], vb = sv[ixj];
                int   ia = si[t], ib = si[ixj];
                bool sw = up ? pair_gt(va, ia, vb, ib) : pair_gt(vb, ib, va, ia);
                if (sw) { sv[t] = vb; si[t] = ib; sv[ixj] = va; si[ixj] = ia; }
            }
            __syncthreads();
        }
    }
}

__global__ void sort_w_kernel() {
    __shared__ float sv[256];
    __shared__ int   si[256];
    int blk = blockIdx.x;
    int b = blk / (CH_*H_);
    int c = (blk / H_) % CH_;
    int h = blk % H_;
    int t = threadIdx.x;
    float* base = g_xcat + ((size_t)(b*C_ + c))*HWv + (size_t)h*W_;
    sv[t] = base[t];
    si[t] = t;
    __syncthreads();
    bitonic256(sv, si);
    base[t] = sv[t];
    g_invw[((size_t)(b*CH_ + c))*HWv + (size_t)h*W_ + si[t]] = t;
}

// ---------------- conv1x1 (split input/output) ----------------
__global__ void __launch_bounds__(256)
conv1x1_kernel(const float* __restrict__ inA, const float* __restrict__ inB,
               const float* __restrict__ w,
               float* __restrict__ outA, float* __restrict__ outB,
               int OC, int oc_split) {
    extern __shared__ float sm[];
    float* Xs = sm;                 // [64][256]
    float* Ws = sm + 64*CV_PX;      // [64][64]
    int p0  = blockIdx.x * CV_PX;
    int oc0 = blockIdx.y * 64;
    int b   = blockIdx.z;
    int t   = threadIdx.x;
#pragma unroll
    for (int r = 0; r < 16; r++) {
        int l = r*256 + t; int ic = l >> 6; int grp = l & 63;
        const float* src = (ic < 32) ? inA : inB;
        *(float4*)&Xs[ic*CV_PX + grp*4] =
            *(const float4*)&src[((size_t)(b*64 + ic))*HWv + p0 + grp*4];
    }
#pragma unroll
    for (int r = 0; r < 16; r++) {
        int l = r*256 + t; int oc = l >> 6; int ic = l & 63;
        Ws[ic*64 + oc] = w[(size_t)(oc0 + oc)*64 + ic];
    }
    __syncthreads();
    int tx = t & 31, ty = t >> 5;
    float acc[8][8];
#pragma unroll
    for (int i = 0; i < 8; i++)
#pragma unroll
        for (int j = 0; j < 8; j++) acc[i][j] = 0.f;
#pragma unroll
    for (int ic = 0; ic < 64; ic++) {
        float4 xa = *(const float4*)&Xs[ic*CV_PX + tx*4];
        float4 xb = *(const float4*)&Xs[ic*CV_PX + 128 + tx*4];
        float4 wa = *(const float4*)&Ws[ic*64 + ty*8];
        float4 wb = *(const float4*)&Ws[ic*64 + ty*8 + 4];
        float xv[8] = {xa.x,xa.y,xa.z,xa.w,xb.x,xb.y,xb.z,xb.w};
        float wv[8] = {wa.x,wa.y,wa.z,wa.w,wb.x,wb.y,wb.z,wb.w};
#pragma unroll
        for (int i = 0; i < 8; i++)
#pragma unroll
            for (int j = 0; j < 8; j++) acc[i][j] += wv[i]*xv[j];
    }
#pragma unroll
    for (int i = 0; i < 8; i++) {
        int oc = oc0 + ty*8 + i;
        float* dst = (oc < oc_split) ? outA : outB;
        size_t ob = ((size_t)(b*OC + oc))*HWv + p0;
        *(float4*)&dst[ob + tx*4]       = make_float4(acc[i][0],acc[i][1],acc[i][2],acc[i][3]);
        *(float4*)&dst[ob + 128 + tx*4] = make_float4(acc[i][4],acc[i][5],acc[i][6],acc[i][7]);
    }
}

// ---------------- depthwise 3x3: qk planes -> split float2 pairs ----------------
__global__ void __launch_bounds__(256)
dwconv_qk_kernel(const float* __restrict__ in, const float* __restrict__ wd) {
    __shared__ float tile[4][10][W_];   // 40KB
    int bid = blockIdx.x;
    int hblk = bid & 31;
    int cb = bid >> 5;
    int c = cb % 64;
    int b = cb / 64;
    int h0 = hblk * 8;
    int t = threadIdx.x;
#pragma unroll
    for (int p = 0; p < 4; p++) {
        const float* ip = in + ((size_t)(b*QKVC + p*64 + c))*HWv;
#pragma unroll
        for (int r = 0; r < 10; r++) {
            int hh = h0 - 1 + r;
            tile[p][r][t] = (hh >= 0 && hh < H_) ? ip[(size_t)hh*W_ + t] : 0.f;
        }
    }
    __syncthreads();

    float o[4][8];
#pragma unroll
    for (int p = 0; p < 4; p++) {
        float wreg[9];
#pragma unroll
        for (int i = 0; i < 9; i++) wreg[i] = __ldg(&wd[(size_t)(p*64 + c)*9 + i]);
        float wl[10], wm[10], wr[10];
#pragma unroll
        for (int r = 0; r < 10; r++) {
            wm[r] = tile[p][r][t];
            wl[r] = (t > 0)   ? tile[p][r][t-1] : 0.f;
            wr[r] = (t < 255) ? tile[p][r][t+1] : 0.f;
        }
#pragma unroll
        for (int r = 0; r < 8; r++) {
            o[p][r] = wl[r  ]*wreg[0] + wm[r  ]*wreg[1] + wr[r  ]*wreg[2]
                    + wl[r+1]*wreg[3] + wm[r+1]*wreg[4] + wr[r+1]*wreg[5]
                    + wl[r+2]*wreg[6] + wm[r+2]*wreg[7] + wr[r+2]*wreg[8];
        }
    }
    float2* op1 = g_qk1 + ((size_t)(b*64 + c))*HWv;
    float2* op2 = g_qk2 + ((size_t)(b*64 + c))*HWv;
#pragma unroll
    for (int r = 0; r < 8; r++) {
        op1[(h0 + r)*W_ + t] = make_float2(o[0][r], o[1][r]);
        op2[(h0 + r)*W_ + t] = make_float2(o[2][r], o[3][r]);
    }
}

// ---------------- depthwise 3x3: v channels -> keys + digit-0 histogram ----------------
__global__ void __launch_bounds__(256)
dwconv_v_kernel(const float* __restrict__ in, const float* __restrict__ wd) {
    __shared__ float tile[10][W_];
    __shared__ unsigned hloc[256];
    int bid = blockIdx.x;
    int hblk = bid & 31;
    int cb = bid >> 5;
    int c = cb % 64;
    int b = cb / 64;
    int ch = 256 + c;
    int h0 = hblk * 8;
    int t = threadIdx.x;
    hloc[t] = 0;
    const float* ip = in + ((size_t)(b*QKVC + ch))*HWv;
#pragma unroll
    for (int r = 0; r < 10; r++) {
        int hh = h0 - 1 + r;
        tile[r][t] = (hh >= 0 && hh < H_) ? ip[(size_t)hh*W_ + t] : 0.f;
    }
    float wreg[9];
#pragma unroll
    for (int i = 0; i < 9; i++) wreg[i] = __ldg(&wd[(size_t)ch*9 + i]);
    __syncthreads();

    float wl[10], wm[10], wr[10];
#pragma unroll
    for (int r = 0; r < 10; r++) {
        wm[r] = tile[r][t];
        wl[r] = (t > 0)   ? tile[r][t-1] : 0.f;
        wr[r] = (t < 255) ? tile[r][t+1] : 0.f;
    }
    int row = b*64 + c;
    unsigned* kp = g_keyA + (size_t)row*HWv;
#pragma unroll
    for (int r = 0; r < 8; r++) {
        float s = wl[r  ]*wreg[0] + wm[r  ]*wreg[1] + wr[r  ]*wreg[2]
                + wl[r+1]*wreg[3] + wm[r+1]*wreg[4] + wr[r+1]*wreg[5]
                + wl[r+2]*wreg[6] + wm[r+2]*wreg[7] + wr[r+2]*wreg[8];
        unsigned u = __float_as_uint(s);
        u ^= (u & 0x80000000u) ? 0xFFFFFFFFu : 0x80000000u;
        kp[(h0 + r)*W_ + t] = u;
        atomicAdd(&hloc[u & 255u], 1u);
    }
    __syncthreads();
    int seg = hblk >> 1;
    unsigned v = hloc[t];
    if (v) atomicAdd(&g_histA[((size_t)row*256 + t)*R_NSEG + seg], v);
}

// ---------------- rhist (passes 2-4) ----------------
__global__ void rhist_kernel(const unsigned* __restrict__ src, unsigned* __restrict__ hist,
                             int shift) {
    __shared__ unsigned h[256];
    int row = blockIdx.x >> 4, seg = blockIdx.x & 15;
    int tid = threadIdx.x;
    if (tid < 256) h[tid] = 0;
    __syncthreads();
    const uint4* s = (const uint4*)(src + (size_t)row*R_N + (size_t)seg*R_SEG);
#pragma unroll
    for (int r = 0; r < 2; r++) {
        uint4 k4 = s[r*R_THREADS + tid];
        atomicAdd(&h[(k4.x >> shift) & 255u], 1u);
        atomicAdd(&h[(k4.y >> shift) & 255u], 1u);
        atomicAdd(&h[(k4.z >> shift) & 255u], 1u);
        atomicAdd(&h[(k4.w >> shift) & 255u], 1u);
    }
    __syncthreads();
    if (tid < 256)
        hist[((size_t)row*256 + tid)*R_NSEG + seg] = h[tid];
}

// ---------------- scan ----------------
__global__ void rscan_kernel(unsigned* __restrict__ hist) {
    int row = blockIdx.x, dg = threadIdx.x;
    unsigned* hp = hist + ((size_t)row*256 + dg)*R_NSEG;
    unsigned v[R_NSEG]; unsigned tot = 0;
#pragma unroll
    for (int s2 = 0; s2 < R_NSEG; s2++) { unsigned t = hp[s2]; v[s2] = tot; tot += t; }
    unsigned lane = dg & 31, w = dg >> 5;
    unsigned x = tot;
#pragma unroll
    for (int o = 1; o < 32; o <<= 1) { unsigned y = __shfl_up_sync(0xffffffffu, x, o); if (lane >= o) x += y; }
    __shared__ unsigned wsum[8];
    if (lane == 31) wsum[w] = x;
    __syncthreads();
    if (dg == 0) { unsigned run = 0; for (int i = 0; i < 8; i++) { unsigned t = wsum[i]; wsum[i] = run; run += t; } }
    __syncthreads();
    unsigned base0 = (x - tot) + wsum[w];
#pragma unroll
    for (int s2 = 0; s2 < R_NSEG; s2++) hp[s2] = base0 + v[s2];
}

// mode: 1 = first pass (generate payload), 0 = middle, 2 = final (emit idx+vs)
__global__ void __launch_bounds__(R_THREADS)
rscatter_kernel(const unsigned* __restrict__ skeys,
                const unsigned short* __restrict__ spids,
                unsigned* __restrict__ dkeys,
                unsigned short* __restrict__ dpids,
                const unsigned* __restrict__ hist,
                int shift, int mode) {
    __shared__ unsigned base[256];
    __shared__ unsigned bb0[256];
    __shared__ unsigned delta[256];
    __shared__ unsigned scanbuf[8];
    __shared__ unsigned skey[R_SEG];          // 16KB; doubles as woff
    __shared__ unsigned short spid[R_SEG];    // 8KB;  doubles as wcnt
    unsigned short* wcnt = spid;
    unsigned*       woff = skey;
    unsigned*       wc32 = (unsigned*)wcnt;

    int row = blockIdx.x >> 4, seg = blockIdx.x & 15;
    int tid = threadIdx.x, w = tid >> 5, lane = tid & 31;
    const unsigned* sk = skeys + (size_t)row*R_N + (size_t)seg*R_SEG;

    unsigned key[R_EPT];
    unsigned pid[R_EPT];
    unsigned posG[R_EPT];
#pragma unroll
    for (int r = 0; r < R_EPT; r++) key[r] = sk[r*R_THREADS + tid];
    if (mode == 1) {
#pragma unroll
        for (int r = 0; r < R_EPT; r++) pid[r] = seg*R_SEG + r*R_THREADS + tid;
    } else {
        const unsigned short* sp = spids + (size_t)row*R_N + (size_t)seg*R_SEG;
#pragma unroll
        for (int r = 0; r < R_EPT; r++) pid[r] = sp[r*R_THREADS + tid];
    }

    if (tid < 256) {
        unsigned bv = hist[((size_t)row*256 + tid)*R_NSEG + seg];
        base[tid] = bv; bb0[tid] = bv;
    }

#pragma unroll
    for (int r = 0; r < R_EPT; r++) {
        wc32[tid] = 0; wc32[tid + 512] = 0; wc32[tid + 1024] = 0; wc32[tid + 1536] = 0;
        unsigned dg = (key[r] >> shift) & 255u;
        unsigned mask = __match_any_sync(0xffffffffu, dg);
        unsigned lr = __popc(mask & ((1u << lane) - 1u));
        unsigned cnt = __popc(mask);
        __syncthreads();
        if (lr == 0) wcnt[w*256 + dg] = (unsigned short)cnt;
        __syncthreads();
        if (tid < 256) {
            unsigned run = base[tid];
#pragma unroll
            for (int ww = 0; ww < 16; ww++) {
                unsigned c2 = wcnt[ww*256 + tid];
                woff[ww*256 + tid] = run;
                run += c2;
            }
            base[tid] = run;
        }
        __syncthreads();
        posG[r] = woff[w*256 + dg] + lr;
    }
    __syncthreads();

    if (tid < 256) {
        unsigned c = base[tid] - bb0[tid];
        unsigned x = c;
#pragma unroll
        for (int o = 1; o < 32; o <<= 1) { unsigned y = __shfl_up_sync(0xffffffffu, x, o); if (lane >= o) x += y; }
        woff[tid] = x - c;
        if (lane == 31) scanbuf[w] = x;
    }
    __syncthreads();
    if (tid == 0) { unsigned run = 0; for (int i = 0; i < 8; i++) { unsigned t2 = scanbuf[i]; scanbuf[i] = run; run += t2; } }
    __syncthreads();
    if (tid < 256) delta[tid] = bb0[tid] - (woff[tid] + scanbuf[tid >> 5]);
    __syncthreads();

#pragma unroll
    for (int r = 0; r < R_EPT; r++) {
        unsigned dg = (key[r] >> shift) & 255u;
        unsigned loc = posG[r] - delta[dg];
        skey[loc] = key[r];
        spid[loc] = (unsigned short)pid[r];
    }
    __syncthreads();

    if (mode != 2) {
        unsigned* dk = dkeys + (size_t)row*R_N;
        unsigned short* dp = dpids + (size_t)row*R_N;
#pragma unroll
        for (int r = 0; r < R_EPT; r++) {
            unsigned i = r*R_THREADS + tid;
            unsigned k2 = skey[i];
            unsigned dg = (k2 >> shift) & 255u;
            unsigned pos = delta[dg] + i;
            dk[pos] = k2;
            dp[pos] = spid[i];
        }
    } else {
        int*   di = g_idx + (size_t)row*R_N;
        float* dv = g_vs  + (size_t)row*R_N;
#pragma unroll
        for (int r = 0; r < R_EPT; r++) {
            unsigned i = r*R_THREADS + tid;
            unsigned k2 = skey[i];
            unsigned dg = (k2 >> shift) & 255u;
            unsigned pos = delta[dg] + i;
            unsigned u = (k2 & 0x80000000u) ? (k2 ^ 0x80000000u) : ~k2;
            di[pos] = (int)spid[i];
            dv[pos] = __uint_as_float(u);
        }
    }
}

// ---------------- attention: qk (float2-split gather) ----------------
__global__ void qk_kernel() {
    __shared__ float Qs[64][65];
    __shared__ float Ks[64][65];
    __shared__ float nred[2][4][64];
    int t = threadIdx.x;
    int vbh = blockIdx.y;
    int var = vbh >> 3, b = (vbh>>2)&1, h = vbh & 3;
    int ty = t >> 4, tx = t & 15;
    int dn = t & 63, qtr = t >> 6;
    const float2* qkp = var ? g_qk2 : g_qk1;
    float acc[4][4];
#pragma unroll
    for (int i = 0; i < 4; i++)
#pragma unroll
        for (int j = 0; j < 4; j++) acc[i][j] = 0.f;
    float sumq = 0.f, sumk = 0.f;
    int n0 = blockIdx.x * 256;
    for (int tile = 0; tile < 4; tile++) {
        int nb = n0 + tile*64;
#pragma unroll
        for (int rr = 0; rr < 16; rr++) {
            int l = rr*256 + t; int d = l >> 6; int nn = l & 63;
            int c = h*16 + (d>>2), f = d & 3;
            int pos = var ? 4*(nb+nn) + f : f*HWP_ + nb + nn;
            size_t rowb = ((size_t)(b*64 + c))*HWv;
            int j = g_idx[rowb + pos];
            float2 v2 = qkp[rowb + j];
            Qs[d][nn] = v2.x;
            Ks[d][nn] = v2.y;
        }
        __syncthreads();
#pragma unroll
        for (int i = 0; i < 16; i++) {
            float qv = Qs[dn][qtr*16 + i];
            float kv = Ks[dn][qtr*16 + i];
            sumq += qv*qv; sumk += kv*kv;
        }
#pragma unroll 8
        for (int nn = 0; nn < 64; nn++) {
            float qa[4], ka[4];
#pragma unroll
            for (int i = 0; i < 4; i++) { qa[i] = Qs[ty*4+i][nn]; ka[i] = Ks[tx*4+i][nn]; }
#pragma unroll
            for (int i = 0; i < 4; i++)
#pragma unroll
                for (int j = 0; j < 4; j++) acc[i][j] += qa[i]*ka[j];
        }
        __syncthreads();
    }
    nred[0][qtr][dn] = sumq;
    nred[1][qtr][dn] = sumk;
    float* sp = g_Spart + ((size_t)(vbh*QK_SL + blockIdx.x))*4096;
#pragma unroll
    for (int i = 0; i < 4; i++)
#pragma unroll
        for (int j = 0; j < 4; j++)
            sp[(ty*4+i)*64 + tx*4 + j] = acc[i][j];
    __syncthreads();
    if (t < 128) {
        int qk = t >> 6, d = t & 63;
        float s = nred[qk][0][d] + nred[qk][1][d] + nred[qk][2][d] + nred[qk][3][d];
        int bin = (var<<10) | (qk<<9) | (b<<8) | (h<<6) | d;
        g_npart[(size_t)bin*QK_SL + blockIdx.x] = s;
    }
}

__global__ void reduce_norm_kernel() {
    int bin = blockIdx.x * 128 + threadIdx.x;
    const float* p = g_npart + (size_t)bin*QK_SL;
    float s = 0.f;
#pragma unroll
    for (int i = 0; i < QK_SL; i++) s += p[i];
    g_norm[bin] = 1.0f / fmaxf(sqrtf(s), 1e-12f);
}

__global__ void softmax_kernel(const float* __restrict__ temp) {
    int blk = blockIdx.x;
    int vbh = blk >> 6, d = blk & 63;
    int var = vbh >> 3, b = (vbh>>2)&1, h = vbh & 3;
    int e = threadIdx.x;
    float sk = g_norm[(var<<10) | (1<<9) | (b<<8) | (h<<6) | e];
    float invq = g_norm[(var<<10) | (b<<8) | (h<<6) | d];
    float T = temp[h];
    const float* sp = g_Spart + (size_t)vbh*QK_SL*4096 + d*64 + e;
    float s = 0.f;
#pragma unroll
    for (int sl = 0; sl < QK_SL; sl++) s += sp[(size_t)sl*4096];
    float ex = expf(s * invq * sk * T);
    __shared__ float red[64];
    red[e] = ex;
    __syncthreads();
    if (e < 32) {
        float p = red[e] + red[e + 32];
#pragma unroll
        for (int o = 16; o > 0; o >>= 1) p += __shfl_down_sync(0xffffffffu, p, o);
        if (e == 0) red[0] = p;
    }
    __syncthreads();
    float r = 1.0f / (red[0] + 1.0f);
    g_attn[(size_t)vbh*4096 + d*64 + e] = ex * r;
}

// av var=0: writes g_out1
__global__ void av0_kernel() {
    __shared__ float As[4096];
    int t = threadIdx.x;
    int bid = blockIdx.x;                 // 512: (b,h,nblk)
    int nblk = bid & 63;
    int h = (bid>>6)&3, b = (bid>>8)&1;
    int vbh = (b<<2) | h;
    for (int l = t; l < 4096; l += 256) As[l] = g_attn[(size_t)vbh*4096 + l];
    __syncthreads();
    int n = nblk*256 + t;
    float acc[64];
#pragma unroll
    for (int d2 = 0; d2 < 64; d2++) acc[d2] = 0.f;
#pragma unroll 4
    for (int e0 = 0; e0 < 64; e0 += 4) {
        int ce = h*16 + (e0 >> 2);
        size_t cb = ((size_t)(b*64 + ce))*HWv;
        float v0 = g_vs[cb + n];
        float v1 = g_vs[cb + HWP_ + n];
        float v2 = g_vs[cb + 2*HWP_ + n];
        float v3 = g_vs[cb + 3*HWP_ + n];
#pragma unroll
        for (int d2 = 0; d2 < 64; d2++) {
            float4 a = *(const float4*)&As[d2*64 + e0];
            acc[d2] += a.x*v0 + a.y*v1 + a.z*v2 + a.w*v3;
        }
    }
#pragma unroll 1
    for (int d2 = 0; d2 < 64; d2++) {
        int cd = h*16 + (d2>>2), fd = d2 & 3;
        g_out1[((size_t)(b*64 + cd))*HWv + (size_t)fd*HWP_ + n] = acc[d2];
    }
}

// av var=1 fused with product + scatter
__global__ void av1_kernel() {
    __shared__ float As[4096];
    int t = threadIdx.x;
    int bid = blockIdx.x;                 // 512
    int nblk = bid & 63;
    int h = (bid>>6)&3, b = (bid>>8)&1;
    int vbh = 8 | (b<<2) | h;
    for (int l = t; l < 4096; l += 256) As[l] = g_attn[(size_t)vbh*4096 + l];
    __syncthreads();
    int n = nblk*256 + t;
    float acc[64];
#pragma unroll
    for (int d2 = 0; d2 < 64; d2++) acc[d2] = 0.f;
#pragma unroll 4
    for (int e0 = 0; e0 < 64; e0 += 4) {
        int ce = h*16 + (e0 >> 2);
        size_t cb = ((size_t)(b*64 + ce))*HWv;
        float4 vv = *(const float4*)&g_vs[cb + 4*(size_t)n];
#pragma unroll
        for (int d2 = 0; d2 < 64; d2++) {
            float4 a = *(const float4*)&As[d2*64 + e0];
            acc[d2] += a.x*vv.x + a.y*vv.y + a.z*vv.z + a.w*vv.w;
        }
    }
#pragma unroll 1
    for (int cg = 0; cg < 16; cg++) {
        int cd = h*16 + cg;
        size_t rb = ((size_t)(b*64 + cd))*HWv;
        size_t pos = rb + 4*(size_t)n;
        float4 o1 = *(const float4*)&g_out1[pos];
        int4   j4 = *(const int4*)&g_idx[pos];
        g_prod[rb + j4.x] = acc[cg*4 + 0] * o1.x;
        g_prod[rb + j4.y] = acc[cg*4 + 1] * o1.y;
        g_prod[rb + j4.z] = acc[cg*4 + 2] * o1.z;
        g_prod[rb + j4.w] = acc[cg*4 + 3] * o1.w;
    }
}

// ---------------- fused unsort (ch<32 only) ----------------
__global__ void unsort_kernel(float* __restrict__ out) {
    size_t gid = (size_t)blockIdx.x*256 + threadIdx.x;   // B*CH*HW
    size_t bc = gid / HWv;
    int b = (int)(bc / CH_), c = (int)(bc % CH_);
    int p = (int)(gid % HWv);
    int j = p & 255;
    int r = g_invh[bc*HWv + p];
    int jw = g_invw[bc*HWv + (size_t)r*W_ + j];
    out[((size_t)(b*C_ + c))*HWv + p] = g_proj[((size_t)(b*C_ + c))*HWv + (size_t)r*W_ + jw];
}

// ---------------- launch ----------------
extern "C" void kernel_launch(void* const* d_in, const int* in_sizes, int n_in,
                              void* d_out, int out_size) {
    const float* x     = (const float*)d_in[0];
    const float* qkvw  = (const float*)d_in[1];
    const float* dww   = (const float*)d_in[2];
    const float* projw = (const float*)d_in[3];
    const float* temp  = (const float*)d_in[4];
    float* out = (float*)d_out;

    cudaFuncSetAttribute((const void*)conv1x1_kernel,
                         cudaFuncAttributeMaxDynamicSharedMemorySize, CV_SMEM);
    cudaFuncSetAttribute((const void*)sort_h_kernel,
                         cudaFuncAttributeMaxDynamicSharedMemorySize, SH_SMEM);

    float *p_xcat, *p_qkvpre, *p_prod, *p_proj;
    unsigned *p_kA, *p_kB, *p_hA, *p_hB;
    unsigned short *p_pA, *p_pB;
    cudaGetSymbolAddress((void**)&p_xcat,   g_xcat);
    cudaGetSymbolAddress((void**)&p_qkvpre, g_qkv_pre);
    cudaGetSymbolAddress((void**)&p_prod,   g_prod);
    cudaGetSymbolAddress((void**)&p_proj,   g_proj);
    cudaGetSymbolAddress((void**)&p_kA,     g_keyA);
    cudaGetSymbolAddress((void**)&p_kB,     g_keyB);
    cudaGetSymbolAddress((void**)&p_pA,     g_pidA);
    cudaGetSymbolAddress((void**)&p_pB,     g_pidB);
    cudaGetSymbolAddress((void**)&p_hA,     g_histA);
    cudaGetSymbolAddress((void**)&p_hB,     g_histB);

    const int NBCH = (B_*CH_*HWv) / 256;    // 16384

    // stage A: zero histA + small sorts
    zero_histA_kernel<<<(R_ROWS*256*R_NSEG)/256, 256>>>();
    sort_h_kernel<<<B_*CH_*(W_/32), 256, SH_SMEM>>>(x);
    sort_w_kernel<<<B_*CH_*H_, 256>>>();

    // stage B: convs (dwconv_v emits keys + digit-0 histogram into histA)
    conv1x1_kernel<<<dim3(HWv/CV_PX, QKVC/64, B_), 256, CV_SMEM>>>(
        p_xcat, x, qkvw, p_qkvpre, p_qkvpre, QKVC, QKVC);
    dwconv_v_kernel <<<B_*64*32, 256>>>(p_qkvpre, dww);
    dwconv_qk_kernel<<<B_*64*32, 256>>>(p_qkvpre, dww);

    // stage C: big stable argsort (pass-1 hist fused into dwconv_v)
    {
        const int NB = R_ROWS * R_NSEG;   // 2048
        rscan_kernel<<<R_ROWS, 256>>>(p_hA);
        rscatter_kernel<<<NB, R_THREADS>>>(p_kA, (const unsigned short*)0, p_kB, p_pB,
                                           p_hA, 0, 1);
        rhist_kernel<<<NB, R_THREADS>>>(p_kB, p_hB, 8);
        rscan_kernel<<<R_ROWS, 256>>>(p_hB);
        rscatter_kernel<<<NB, R_THREADS>>>(p_kB, p_pB, p_kA, p_pA, p_hB, 8, 0);

        rhist_kernel<<<NB, R_THREADS>>>(p_kA, p_hA, 16);
        rscan_kernel<<<R_ROWS, 256>>>(p_hA);
        rscatter_kernel<<<NB, R_THREADS>>>(p_kA, p_pA, p_kB, p_pB, p_hA, 16, 0);

        rhist_kernel<<<NB, R_THREADS>>>(p_kB, p_hB, 24);
        rscan_kernel<<<R_ROWS, 256>>>(p_hB);
        rscatter_kernel<<<NB, R_THREADS>>>(p_kB, p_pB, (unsigned*)0, (unsigned short*)0,
                                           p_hB, 24, 2);
    }

    // stage D: attention
    qk_kernel<<<dim3(QK_SL, 16), 256>>>();
    reduce_norm_kernel<<<16, 128>>>();
    softmax_kernel<<<16*64, 64>>>(temp);
    av0_kernel<<<512, 256>>>();
    av1_kernel<<<512, 256>>>();

    // stage E: epilogue
    conv1x1_kernel<<<dim3(HWv/CV_PX, 1, B_), 256, CV_SMEM>>>(
        p_prod, p_prod, projw, p_proj, out, C_, CH_);
    unsort_kernel<<<NBCH, 256>>>(out);
}